// round 3
// baseline (speedup 1.0000x reference)
#include <cuda_runtime.h>
#include <cuda_bf16.h>

// BandedJointEncoder: closed-form inverse of per-(b,z) upper-bidiagonal U.
//   d[t] = mapped[b,t,32+2z] + 1 ; s[t] = mapped[b,t,33+2z]
//   L[r,c] = inv_d[r] * prod_{k=c}^{r-1} (-s_k/d_k)  for r >= c, else 0
// Outputs: mean [B,Z,T] then cov_tril_lower [B,Z,T,T].
//
// R2: parallelism fix. grid = (B*Z, 4): each CTA owns 128 rows of one (b,z).
// 512 threads = 4 sub-rowgroups (32 rows) x 128 column-quads; STG.128 per row.
// All 148 SMs active, ~3.5 CTAs/SM resident -> more store streams in flight.

#define T_DIM 512
#define Z_DIM 32
#define C_DIM 96

__global__ __launch_bounds__(512)
void banded_joint_encoder_kernel(const float* __restrict__ in,
                                 float* __restrict__ out_mean,
                                 float* __restrict__ out_cov)
{
    const int bz  = blockIdx.x;          // b*Z + z
    const int b   = bz >> 5;
    const int z   = bz & 31;
    const int tid = threadIdx.x;

    __shared__ float2 sh_ti[T_DIM];      // {t[k], inv_d[k]}
    __shared__ float  sh_b8[T_DIM / 8];  // 8-term block products of t

    // ---- prologue: per-row t / inv_d; mean output from gy==0 CTAs only ----
    {
        const float* row_in = in + ((size_t)b * T_DIM + tid) * C_DIM;
        float dv  = row_in[32 + 2 * z] + 1.0f;
        float sv  = row_in[33 + 2 * z];
        float inv = 1.0f / dv;
        sh_ti[tid] = make_float2(-sv * inv, inv);
        if (blockIdx.y == 0)
            out_mean[(size_t)bz * T_DIM + tid] = row_in[z];
    }
    __syncthreads();

    if (tid < T_DIM / 8) {
        int k0 = tid * 8;
        float bprod = sh_ti[k0].x;
        #pragma unroll
        for (int j = 1; j < 8; ++j) bprod *= sh_ti[k0 + j].x;
        sh_b8[tid] = bprod;
    }
    __syncthreads();

    const int sub = tid >> 7;                       // 0..3 within CTA
    const int l   = tid & 127;                      // column quad 0..127
    const int c0  = l << 2;                         // first owned column
    const int R0  = (blockIdx.y << 7) + (sub << 5); // first of 32 rows

    // ---- seed running products p_j = prod_{k=c0+j}^{R0-1} t_k ----
    float p3 = 1.f;
    {
        int k = c0 + 3;
        if (k < R0) {
            int e = (k + 7) & ~7;        // R0 % 8 == 0, so e <= R0
            for (; k < e; ++k)           p3 *= sh_ti[k].x;
            for (; k + 8 <= R0; k += 8)  p3 *= sh_b8[k >> 3];
        }
    }
    float p2 = (c0 + 2 < R0) ? sh_ti[c0 + 2].x * p3 : 1.f;
    float p1 = (c0 + 1 < R0) ? sh_ti[c0 + 1].x * p2 : 1.f;
    float p0 = (c0     < R0) ? sh_ti[c0    ].x * p1 : 1.f;

    // ---- main loop: 32 rows, one STG.128 per row per thread ----
    float4* out4 = (float4*)(out_cov + (size_t)bz * T_DIM * T_DIM) + l;

    #pragma unroll 4
    for (int r = R0; r < R0 + 32; ++r) {
        const float2 ti = sh_ti[r];      // broadcast LDS.64, conflict-free
        const float tv = ti.x, iv = ti.y;

        float4 v;
        bool a0 = (r >= c0);
        bool a1 = (r >= c0 + 1);
        bool a2 = (r >= c0 + 2);
        bool a3 = (r >= c0 + 3);
        v.x = a0 ? p0 * iv : 0.f;
        v.y = a1 ? p1 * iv : 0.f;
        v.z = a2 ? p2 * iv : 0.f;
        v.w = a3 ? p3 * iv : 0.f;
        if (a0) p0 *= tv;
        if (a1) p1 *= tv;
        if (a2) p2 *= tv;
        if (a3) p3 *= tv;

        out4[(size_t)r * (T_DIM / 4)] = v;
    }
}

extern "C" void kernel_launch(void* const* d_in, const int* in_sizes, int n_in,
                              void* d_out, int out_size)
{
    const float* in = (const float*)d_in[0];
    float* out = (float*)d_out;

    const int B = in_sizes[0] / (T_DIM * C_DIM);

    float* out_mean = out;                                // [B, Z, T]
    float* out_cov  = out + (size_t)B * Z_DIM * T_DIM;    // [B, Z, T, T]

    dim3 grid(B * Z_DIM, 4);
    banded_joint_encoder_kernel<<<grid, 512>>>(in, out_mean, out_cov);
}

// round 4
// speedup vs baseline: 1.0088x; 1.0088x over previous
#include <cuda_runtime.h>
#include <cuda_bf16.h>
#include <cstdint>

// BandedJointEncoder: closed-form inverse of per-(b,z) upper-bidiagonal U.
//   d[t] = mapped[b,t,32+2z] + 1 ; s[t] = mapped[b,t,33+2z]
//   L[r,c] = inv_d[r] * prod_{k=c}^{r-1} (-s_k/d_k)  for r >= c, else 0
// Outputs: mean [B,Z,T] then cov_tril_lower [B,Z,T,T].
//
// R3: STG write-path ceiling experiment. All-STG variants pin L2 at ~50%
// (~3000 B/cyc write cap). Switch stores to TMA bulk (cp.async.bulk
// shared->global), which bypasses L1tex: compute 16-row chunks into a
// double-buffered SMEM staging area, bulk-store 32KB per chunk.

#define T_DIM 512
#define Z_DIM 32
#define C_DIM 96
#define ROWS_PER_CTA 256
#define CHUNK_ROWS 16
#define CHUNK_FLOATS (CHUNK_ROWS * T_DIM)            // 8192
#define CHUNK_BYTES  (CHUNK_FLOATS * 4)              // 32768
#define NCHUNKS (ROWS_PER_CTA / CHUNK_ROWS)          // 16

__device__ __forceinline__ uint32_t smem_u32(const void* p) {
    uint32_t a;
    asm("{ .reg .u64 t; cvta.to.shared.u64 t, %1; cvt.u32.u64 %0, t; }"
        : "=r"(a) : "l"(p));
    return a;
}

__global__ __launch_bounds__(T_DIM)
void banded_joint_encoder_kernel(const float* __restrict__ in,
                                 float* __restrict__ out_mean,
                                 float* __restrict__ out_cov)
{
    extern __shared__ float sh_buf[];    // 2 * CHUNK_FLOATS

    const int bz  = blockIdx.x;          // b*Z + z
    const int b   = bz >> 5;
    const int z   = bz & 31;
    const int c   = threadIdx.x;         // owned column 0..511

    __shared__ float2 sh_ti[T_DIM];      // {t[k], inv_d[k]}
    __shared__ float  sh_b8[T_DIM / 8];  // 8-term block products of t

    // ---- prologue ----
    {
        const float* row_in = in + ((size_t)b * T_DIM + c) * C_DIM;
        float dv  = row_in[32 + 2 * z] + 1.0f;
        float sv  = row_in[33 + 2 * z];
        float inv = 1.0f / dv;
        sh_ti[c] = make_float2(-sv * inv, inv);
        if (blockIdx.y == 0)
            out_mean[(size_t)bz * T_DIM + c] = row_in[z];
    }
    __syncthreads();

    if (c < T_DIM / 8) {
        int k0 = c * 8;
        float bprod = sh_ti[k0].x;
        #pragma unroll
        for (int j = 1; j < 8; ++j) bprod *= sh_ti[k0 + j].x;
        sh_b8[c] = bprod;
    }
    __syncthreads();

    const int R0 = blockIdx.y * ROWS_PER_CTA;

    // ---- seed running product p = prod_{k=c}^{R0-1} t_k (R0 % 8 == 0) ----
    float p = 1.f;
    if (c < R0) {
        int k = c;
        int e = (k + 7) & ~7;
        if (e > R0) e = R0;
        for (; k < e; ++k)          p *= sh_ti[k].x;
        for (; k + 8 <= R0; k += 8) p *= sh_b8[k >> 3];
    }

    float* gbase = out_cov + (size_t)bz * T_DIM * T_DIM;

    // ---- main loop: compute chunk into SMEM, TMA bulk store ----
    for (int chunk = 0; chunk < NCHUNKS; ++chunk) {
        float* buf = sh_buf + (chunk & 1) * CHUNK_FLOATS;
        const int r0 = R0 + chunk * CHUNK_ROWS;

        // wait for the bulk store that last read this buffer (2 chunks ago)
        if (chunk >= 2) {
            if (c == 0)
                asm volatile("cp.async.bulk.wait_group %0;" :: "n"(1) : "memory");
            __syncthreads();
        }

        #pragma unroll
        for (int j = 0; j < CHUNK_ROWS; ++j) {
            const int r = r0 + j;
            const float2 ti = sh_ti[r];          // broadcast LDS.64
            const bool a = (r >= c);
            buf[j * T_DIM + c] = a ? p * ti.y : 0.f;
            if (a) p *= ti.x;
        }
        __syncthreads();

        if (c == 0) {
            asm volatile("fence.proxy.async.shared::cta;" ::: "memory");
            asm volatile(
                "cp.async.bulk.global.shared::cta.bulk_group [%0], [%1], %2;"
                :: "l"(gbase + (size_t)r0 * T_DIM),
                   "r"(smem_u32(buf)),
                   "r"((uint32_t)CHUNK_BYTES)
                : "memory");
            asm volatile("cp.async.bulk.commit_group;" ::: "memory");
        }
    }

    // drain all pending bulk stores before exit
    if (c == 0)
        asm volatile("cp.async.bulk.wait_group %0;" :: "n"(0) : "memory");
}

extern "C" void kernel_launch(void* const* d_in, const int* in_sizes, int n_in,
                              void* d_out, int out_size)
{
    const float* in = (const float*)d_in[0];
    float* out = (float*)d_out;

    const int B = in_sizes[0] / (T_DIM * C_DIM);

    float* out_mean = out;                                // [B, Z, T]
    float* out_cov  = out + (size_t)B * Z_DIM * T_DIM;    // [B, Z, T, T]

    static_assert(2 * CHUNK_BYTES == 65536, "smem size");
    cudaFuncSetAttribute(banded_joint_encoder_kernel,
                         cudaFuncAttributeMaxDynamicSharedMemorySize,
                         2 * CHUNK_BYTES);

    dim3 grid(B * Z_DIM, T_DIM / ROWS_PER_CTA);           // (128, 2)
    banded_joint_encoder_kernel<<<grid, T_DIM, 2 * CHUNK_BYTES>>>(
        in, out_mean, out_cov);
}

// round 5
// speedup vs baseline: 1.1737x; 1.1635x over previous
#include <cuda_runtime.h>
#include <cuda_bf16.h>

// BandedJointEncoder: closed-form inverse of per-(b,z) upper-bidiagonal U.
//   d[t] = mapped[b,t,32+2z] + 1 ; s[t] = mapped[b,t,33+2z]
//   L[r,c] = inv_d[r] * prod_{k=c}^{r-1} (-s_k/d_k)  for r >= c, else 0
// Outputs: mean [B,Z,T] then cov_tril_lower [B,Z,T,T].
//
// R5 = R2 (best wall-clock config: grid=B*Z, 512 thr, STG.128, single wave)
//      + streaming store hint (__stcs): output is write-once and larger than
//      L2, so evict-first policy smooths steady-state dirty-line drain,
//      which R4 analysis identified as the binder.

#define T_DIM 512
#define Z_DIM 32
#define C_DIM 96

__global__ __launch_bounds__(T_DIM)
void banded_joint_encoder_kernel(const float* __restrict__ in,
                                 float* __restrict__ out_mean,
                                 float* __restrict__ out_cov)
{
    const int bz  = blockIdx.x;          // b*Z + z
    const int b   = bz >> 5;
    const int z   = bz & 31;
    const int tid = threadIdx.x;

    __shared__ float2 sh_ti[T_DIM];      // {t[k], inv_d[k]}
    __shared__ float  sh_b8[T_DIM / 8];  // 8-term block products of t

    // ---- prologue: per-row t / inv_d, mean output ----
    {
        const float* row_in = in + ((size_t)b * T_DIM + tid) * C_DIM;
        float dv  = row_in[32 + 2 * z] + 1.0f;
        float sv  = row_in[33 + 2 * z];
        float inv = 1.0f / dv;
        sh_ti[tid] = make_float2(-sv * inv, inv);
        out_mean[(size_t)bz * T_DIM + tid] = row_in[z];
    }
    __syncthreads();

    if (tid < T_DIM / 8) {
        int k0 = tid * 8;
        float bprod = sh_ti[k0].x;
        #pragma unroll
        for (int j = 1; j < 8; ++j) bprod *= sh_ti[k0 + j].x;
        sh_b8[tid] = bprod;
    }
    __syncthreads();

    const int g  = tid >> 7;             // row group 0..3
    const int l  = tid & 127;            // column quad 0..127
    const int c0 = l << 2;               // first of 4 owned columns
    const int R0 = g << 7;               // first row of this group

    // ---- seed running products p_j = prod_{k=c0+j}^{R0-1} t_k ----
    float p3 = 1.f;
    {
        int k = c0 + 3;
        if (k < R0) {
            int e = (k + 7) & ~7;        // R0 % 8 == 0 -> e <= R0
            for (; k < e; ++k)          p3 *= sh_ti[k].x;
            for (; k + 8 <= R0; k += 8) p3 *= sh_b8[k >> 3];
        }
    }
    float p2 = (c0 + 2 < R0) ? sh_ti[c0 + 2].x * p3 : 1.f;
    float p1 = (c0 + 1 < R0) ? sh_ti[c0 + 1].x * p2 : 1.f;
    float p0 = (c0     < R0) ? sh_ti[c0    ].x * p1 : 1.f;

    // ---- main loop: 128 rows, one streaming STG.128 per row per thread ----
    float4* out4 = (float4*)(out_cov + (size_t)bz * T_DIM * T_DIM) + l;

    #pragma unroll 4
    for (int r = R0; r < R0 + 128; ++r) {
        const float2 ti = sh_ti[r];      // broadcast LDS.64, conflict-free
        const float tv = ti.x, iv = ti.y;

        float4 v;
        bool a0 = (r >= c0);
        bool a1 = (r >= c0 + 1);
        bool a2 = (r >= c0 + 2);
        bool a3 = (r >= c0 + 3);
        v.x = a0 ? p0 * iv : 0.f;
        v.y = a1 ? p1 * iv : 0.f;
        v.z = a2 ? p2 * iv : 0.f;
        v.w = a3 ? p3 * iv : 0.f;
        if (a0) p0 *= tv;
        if (a1) p1 *= tv;
        if (a2) p2 *= tv;
        if (a3) p3 *= tv;

        __stcs(&out4[(size_t)r * (T_DIM / 4)], v);   // st.global.cs.v4.f32
    }
}

extern "C" void kernel_launch(void* const* d_in, const int* in_sizes, int n_in,
                              void* d_out, int out_size)
{
    const float* in = (const float*)d_in[0];
    float* out = (float*)d_out;

    const int B = in_sizes[0] / (T_DIM * C_DIM);

    float* out_mean = out;                                // [B, Z, T]
    float* out_cov  = out + (size_t)B * Z_DIM * T_DIM;    // [B, Z, T, T]

    banded_joint_encoder_kernel<<<B * Z_DIM, T_DIM>>>(in, out_mean, out_cov);
}